// round 13
// baseline (speedup 1.0000x reference)
#include <cuda_runtime.h>
#include <cuda_bf16.h>
#include <math.h>
#include <stdint.h>

#define T_TOK  8192
#define DM     1024
#define NE     8
#define FH     4096
#define NPAIR  (T_TOK*2)

// Stage layout (16KB): Ah[128m x 32B] +0 | Al +4096 | Bh[16k x 256B] +8192 | Bl +12288
#define STAGE_B 16384

// ---------------- scratch (device globals; 320MB — DO NOT EXCEED) -----------
__device__ int   g_counts[NE];
__device__ int   g_off[NE];
__device__ int   g_pairs[NE][T_TOK];
__device__ float g_cw[NPAIR];
__device__ __align__(256) __nv_bfloat16 g_hh[(size_t)NPAIR * FH];  // hidden hi (128MB)
__device__ __align__(256) __nv_bfloat16 g_hl[(size_t)NPAIR * FH];  // hidden lo (128MB)
__device__ __align__(256) float g_y[(size_t)NPAIR * DM];           // 64MB

// ---------------- helpers ----------------------------------------------------
__device__ __forceinline__ uint32_t smem_u32(const void* p) {
    return (uint32_t)__cvta_generic_to_shared(p);
}
#define CPA16(dst, src) \
    asm volatile("cp.async.cg.shared.global [%0], [%1], 16;" :: "r"(dst), "l"(src) : "memory")
#define CPA_COMMIT() asm volatile("cp.async.commit_group;" ::: "memory")
#define CPA_WAIT_1() asm volatile("cp.async.wait_group 1;" ::: "memory")

__device__ __forceinline__ void ldsm4(uint32_t* r, uint32_t addr) {
    asm volatile("ldmatrix.sync.aligned.m8n8.x4.shared.b16 {%0,%1,%2,%3}, [%4];"
                 : "=r"(r[0]), "=r"(r[1]), "=r"(r[2]), "=r"(r[3]) : "r"(addr));
}
__device__ __forceinline__ void ldsm4_t(uint32_t* r, uint32_t addr) {
    asm volatile("ldmatrix.sync.aligned.m8n8.x4.trans.shared.b16 {%0,%1,%2,%3}, [%4];"
                 : "=r"(r[0]), "=r"(r[1]), "=r"(r[2]), "=r"(r[3]) : "r"(addr));
}
__device__ __forceinline__ void mma_bf16(float* c, const uint32_t* a, const uint32_t* b) {
    asm volatile("mma.sync.aligned.m16n8k16.row.col.f32.bf16.bf16.f32 "
                 "{%0,%1,%2,%3}, {%4,%5,%6,%7}, {%8,%9}, {%0,%1,%2,%3};"
                 : "+f"(c[0]), "+f"(c[1]), "+f"(c[2]), "+f"(c[3])
                 : "r"(a[0]), "r"(a[1]), "r"(a[2]), "r"(a[3]), "r"(b[0]), "r"(b[1]));
}
// split 8 fp32 -> packed bf16 hi/lo (8 each)
__device__ __forceinline__ void split8(const float* v, uint4& h4, uint4& l4) {
    uint32_t h[4], l[4];
    #pragma unroll
    for (int j = 0; j < 4; j++) {
        __nv_bfloat16 h0 = __float2bfloat16(v[2*j]);
        __nv_bfloat16 h1 = __float2bfloat16(v[2*j+1]);
        float r0 = v[2*j]   - __bfloat162float(h0);
        float r1 = v[2*j+1] - __bfloat162float(h1);
        __nv_bfloat16 q0 = __float2bfloat16(r0), q1 = __float2bfloat16(r1);
        h[j] = (uint32_t)__bfloat16_as_ushort(h0) | ((uint32_t)__bfloat16_as_ushort(h1) << 16);
        l[j] = (uint32_t)__bfloat16_as_ushort(q0) | ((uint32_t)__bfloat16_as_ushort(q1) << 16);
    }
    h4 = make_uint4(h[0], h[1], h[2], h[3]);
    l4 = make_uint4(l[0], l[1], l[2], l[3]);
}

// ---------------- small kernels ---------------------------------------------
__global__ void zero_counts_kernel() {
    if (threadIdx.x < NE) g_counts[threadIdx.x] = 0;
}
__global__ void prefix_kernel() {
    if (threadIdx.x == 0) {
        int s = 0;
        for (int e = 0; e < NE; e++) { g_off[e] = s; s += g_counts[e]; }
    }
}

__global__ __launch_bounds__(256) void gate_kernel(const float* __restrict__ x,
                                                   const float* __restrict__ wg) {
    const int t = blockIdx.x * 8 + (threadIdx.x >> 5);
    const int lane = threadIdx.x & 31;
    if (t >= T_TOK) return;
    const float* xr = x + (size_t)t * DM;
    float acc[NE];
    #pragma unroll
    for (int e = 0; e < NE; e++) acc[e] = 0.f;
    for (int d = lane; d < DM; d += 32) {
        const float xv = xr[d];
        #pragma unroll
        for (int e = 0; e < NE; e++) acc[e] += xv * wg[e * DM + d];
    }
    #pragma unroll
    for (int e = 0; e < NE; e++)
        #pragma unroll
        for (int o = 16; o > 0; o >>= 1)
            acc[e] += __shfl_xor_sync(0xffffffffu, acc[e], o);
    if (lane == 0) {
        float m = acc[0];
        #pragma unroll
        for (int e = 1; e < NE; e++) m = fmaxf(m, acc[e]);
        float p[NE], s = 0.f;
        #pragma unroll
        for (int e = 0; e < NE; e++) { p[e] = expf(acc[e] - m); s += p[e]; }
        const float inv = 1.f / s;
        #pragma unroll
        for (int e = 0; e < NE; e++) p[e] *= inv;
        int e0 = 0;
        #pragma unroll
        for (int e = 1; e < NE; e++) if (p[e] > p[e0]) e0 = e;
        int e1 = -1;
        #pragma unroll
        for (int e = 0; e < NE; e++) {
            if (e == e0) continue;
            if (e1 < 0 || p[e] > p[e1]) e1 = e;
        }
        const int ee[2] = { e0, e1 };
        #pragma unroll
        for (int k = 0; k < 2; k++) {
            const int e = ee[k];
            const int idx = atomicAdd(&g_counts[e], 1);
            g_pairs[e][idx] = t * 2 + k;
            g_cw[t * 2 + k] = p[e];
        }
    }
}

// ---------------- GEMM1 mainloop (R11-proven: 2-stage, register-staged) ------
// CTA 128x128, 4 warps (2x2), warp tile 64x64, K chunks of 16.
__device__ __forceinline__ void gemm1_mainloop(
    const float* __restrict__ axp,                  // this thread's x row
    const float* __restrict__ Bsrc, int n0,         // W1 (fp32), stride FH
    char* smem, float (&acc)[4][8][4])
{
    const int NCH = DM / 16;
    const int tid = threadIdx.x;
    const uint32_t sbase = smem_u32(smem);

    const int am = tid;
    const int bk = tid >> 3, bn = tid & 7;
    const uint32_t aswz = (uint32_t)((am >> 2) & 1);
    const uint32_t aoff[2] = { (uint32_t)(am * 32) + ((0u ^ aswz) * 16u),
                               (uint32_t)(am * 32) + ((1u ^ aswz) * 16u) };
    const uint32_t boff[2] = { (uint32_t)(bk * 256 + (((bn    ) ^ (bk & 7)) * 16)),
                               (uint32_t)(bk * 256 + (((bn + 8) ^ (bk & 7)) * 16)) };
    const float* bb0 = Bsrc + (size_t)bk * FH + n0 + bn * 8;
    const float* bb1 = bb0 + 64;

    const int lane = tid & 31, wid = tid >> 5;
    const int wm = (wid >> 1) * 64, wn = (wid & 1) * 64;
    const int rA = wm + (lane & 15);
    const uint32_t offA = (uint32_t)(rA * 32) +
                          ((((lane >> 4) & 1) ^ ((rA >> 2) & 1)) ? 16u : 0u);
    const int bkr = lane & 15;
    const int bnc0 = (wn >> 3) + ((lane >> 4) & 1);

    float ax[16], bx[16];

    #define G1_LDG(c_) do {                                                      \
        const int kb = (c_) * 16;                                                \
        float4 t0 = *(const float4*)(axp + kb);                                  \
        float4 t1 = *(const float4*)(axp + kb + 4);                              \
        float4 t2 = *(const float4*)(axp + kb + 8);                              \
        float4 t3 = *(const float4*)(axp + kb + 12);                             \
        ax[0]=t0.x; ax[1]=t0.y; ax[2]=t0.z; ax[3]=t0.w;                          \
        ax[4]=t1.x; ax[5]=t1.y; ax[6]=t1.z; ax[7]=t1.w;                          \
        ax[8]=t2.x; ax[9]=t2.y; ax[10]=t2.z; ax[11]=t2.w;                        \
        ax[12]=t3.x; ax[13]=t3.y; ax[14]=t3.z; ax[15]=t3.w;                      \
        const float* bp0 = bb0 + (size_t)kb * FH;                                \
        const float* bp1 = bb1 + (size_t)kb * FH;                                \
        float4 u0 = *(const float4*)(bp0);                                       \
        float4 u1 = *(const float4*)(bp0 + 4);                                   \
        float4 u2 = *(const float4*)(bp1);                                       \
        float4 u3 = *(const float4*)(bp1 + 4);                                   \
        bx[0]=u0.x; bx[1]=u0.y; bx[2]=u0.z; bx[3]=u0.w;                          \
        bx[4]=u1.x; bx[5]=u1.y; bx[6]=u1.z; bx[7]=u1.w;                          \
        bx[8]=u2.x; bx[9]=u2.y; bx[10]=u2.z; bx[11]=u2.w;                        \
        bx[12]=u3.x; bx[13]=u3.y; bx[14]=u3.z; bx[15]=u3.w;                      \
    } while (0)

    #define G1_STS(s_) do {                                                      \
        char* st = smem + (s_) * STAGE_B;                                        \
        _Pragma("unroll")                                                        \
        for (int g = 0; g < 2; g++) {                                            \
            uint4 h4, l4; split8(ax + g * 8, h4, l4);                            \
            *(uint4*)(st + aoff[g])        = h4;                                 \
            *(uint4*)(st + 4096 + aoff[g]) = l4;                                 \
            uint4 bh4, bl4; split8(bx + g * 8, bh4, bl4);                        \
            *(uint4*)(st + 8192  + boff[g]) = bh4;                               \
            *(uint4*)(st + 12288 + boff[g]) = bl4;                               \
        }                                                                        \
    } while (0)

    G1_LDG(0);
    for (int c = 0; c < NCH; c++) {
        const int s = c & 1;
        G1_STS(s);
        if (c + 1 < NCH) G1_LDG(c + 1);
        __syncthreads();
        const uint32_t so = sbase + (uint32_t)s * STAGE_B;

        uint32_t ah[4][4], al[4][4], bh[4][4], bl[4][4];
        #pragma unroll
        for (int i = 0; i < 4; i++) {
            ldsm4(ah[i], so + offA + (uint32_t)(i * 16 * 32));
            ldsm4(al[i], so + 4096u + offA + (uint32_t)(i * 16 * 32));
        }
        #pragma unroll
        for (int jp = 0; jp < 4; jp++) {
            const uint32_t bo = (uint32_t)(bkr * 256 +
                                (((bnc0 + jp * 2) ^ (bkr & 7)) * 16));
            ldsm4_t(bh[jp], so + 8192u  + bo);
            ldsm4_t(bl[jp], so + 12288u + bo);
        }
        #pragma unroll
        for (int i = 0; i < 4; i++)
            #pragma unroll
            for (int j = 0; j < 8; j++)
                mma_bf16(acc[i][j], ah[i], &bh[j >> 1][(j & 1) * 2]);
        #pragma unroll
        for (int i = 0; i < 4; i++)
            #pragma unroll
            for (int j = 0; j < 8; j++)
                mma_bf16(acc[i][j], ah[i], &bl[j >> 1][(j & 1) * 2]);
        #pragma unroll
        for (int i = 0; i < 4; i++)
            #pragma unroll
            for (int j = 0; j < 8; j++)
                mma_bf16(acc[i][j], al[i], &bh[j >> 1][(j & 1) * 2]);
    }
    #undef G1_LDG
    #undef G1_STS
}

// ---------------- GEMM2 mainloop (3-stage; A via cp.async, B reg-staged) -----
__device__ __forceinline__ void gemm2_mainloop(
    const __nv_bfloat16* __restrict__ ahp,          // this thread's A-hi row
    const __nv_bfloat16* __restrict__ alp,          // this thread's A-lo row
    const float* __restrict__ Bsrc, int n0,         // W2 (fp32), stride DM
    char* smem, float (&acc)[4][8][4])
{
    const int NCH = FH / 16;
    const int tid = threadIdx.x;
    const uint32_t sbase = smem_u32(smem);

    const int am = tid;
    const int bk = tid >> 3, bn = tid & 7;
    const uint32_t aswz = (uint32_t)((am >> 2) & 1);
    const uint32_t aoff[2] = { (uint32_t)(am * 32) + ((0u ^ aswz) * 16u),
                               (uint32_t)(am * 32) + ((1u ^ aswz) * 16u) };
    const uint32_t boff[2] = { (uint32_t)(bk * 256 + (((bn    ) ^ (bk & 7)) * 16)),
                               (uint32_t)(bk * 256 + (((bn + 8) ^ (bk & 7)) * 16)) };
    const float* bb0 = Bsrc + (size_t)bk * DM + n0 + bn * 8;
    const float* bb1 = bb0 + 64;

    const int lane = tid & 31, wid = tid >> 5;
    const int wm = (wid >> 1) * 64, wn = (wid & 1) * 64;
    const int rA = wm + (lane & 15);
    const uint32_t offA = (uint32_t)(rA * 32) +
                          ((((lane >> 4) & 1) ^ ((rA >> 2) & 1)) ? 16u : 0u);
    const int bkr = lane & 15;
    const int bnc0 = (wn >> 3) + ((lane >> 4) & 1);

    float bx[16];

    #define G2_LDGB(c_) do {                                                     \
        const int kb = (c_) * 16;                                                \
        const float* bp0 = bb0 + (size_t)kb * DM;                                \
        const float* bp1 = bb1 + (size_t)kb * DM;                                \
        float4 u0 = *(const float4*)(bp0);                                       \
        float4 u1 = *(const float4*)(bp0 + 4);                                   \
        float4 u2 = *(const float4*)(bp1);                                       \
        float4 u3 = *(const float4*)(bp1 + 4);                                   \
        bx[0]=u0.x; bx[1]=u0.y; bx[2]=u0.z; bx[3]=u0.w;                          \
        bx[4]=u1.x; bx[5]=u1.y; bx[6]=u1.z; bx[7]=u1.w;                          \
        bx[8]=u2.x; bx[9]=u2.y; bx[10]=u2.z; bx[11]=u2.w;                        \
        bx[12]=u3.x; bx[13]=u3.y; bx[14]=u3.z; bx[15]=u3.w;                      \
    } while (0)

    #define G2_STSB(s_) do {                                                     \
        char* st = smem + (s_) * STAGE_B;                                        \
        _Pragma("unroll")                                                        \
        for (int g = 0; g < 2; g++) {                                            \
            uint4 bh4, bl4; split8(bx + g * 8, bh4, bl4);                        \
            *(uint4*)(st + 8192  + boff[g]) = bh4;                               \
            *(uint4*)(st + 12288 + boff[g]) = bl4;                               \
        }                                                                        \
    } while (0)

    #define G2_CPA(c_, s_) do {                                                  \
        const uint32_t sb = sbase + (uint32_t)(s_) * STAGE_B;                    \
        const int kb = (c_) * 16;                                                \
        _Pragma("unroll")                                                        \
        for (int g = 0; g < 2; g++) {                                            \
            CPA16(sb + aoff[g],         ahp + kb + g * 8);                       \
            CPA16(sb + 4096u + aoff[g], alp + kb + g * 8);                       \
        }                                                                        \
    } while (0)

    // prologue: B chunk0 stored; B chunk1 staged; A chunks 0,1 in flight
    G2_LDGB(0); G2_STSB(0); G2_LDGB(1);
    G2_CPA(0, 0); CPA_COMMIT();
    G2_CPA(1, 1); CPA_COMMIT();

    for (int c = 0; c < NCH; c++) {
        const int s = c % 3;
        CPA_WAIT_1();               // A chunks <= c landed (trailing empties keep count)
        __syncthreads();
        if (c + 1 < NCH) G2_STSB((c + 1) % 3);
        if (c + 2 < NCH) { G2_LDGB(c + 2); G2_CPA(c + 2, (c + 2) % 3); }
        CPA_COMMIT();

        const uint32_t so = sbase + (uint32_t)s * STAGE_B;
        uint32_t ah[4][4], al[4][4], bh[4][4], bl[4][4];
        #pragma unroll
        for (int i = 0; i < 4; i++) {
            ldsm4(ah[i], so + offA + (uint32_t)(i * 16 * 32));
            ldsm4(al[i], so + 4096u + offA + (uint32_t)(i * 16 * 32));
        }
        #pragma unroll
        for (int jp = 0; jp < 4; jp++) {
            const uint32_t bo = (uint32_t)(bkr * 256 +
                                (((bnc0 + jp * 2) ^ (bkr & 7)) * 16));
            ldsm4_t(bh[jp], so + 8192u  + bo);
            ldsm4_t(bl[jp], so + 12288u + bo);
        }
        #pragma unroll
        for (int i = 0; i < 4; i++)
            #pragma unroll
            for (int j = 0; j < 8; j++)
                mma_bf16(acc[i][j], ah[i], &bh[j >> 1][(j & 1) * 2]);
        #pragma unroll
        for (int i = 0; i < 4; i++)
            #pragma unroll
            for (int j = 0; j < 8; j++)
                mma_bf16(acc[i][j], ah[i], &bl[j >> 1][(j & 1) * 2]);
        #pragma unroll
        for (int i = 0; i < 4; i++)
            #pragma unroll
            for (int j = 0; j < 8; j++)
                mma_bf16(acc[i][j], al[i], &bh[j >> 1][(j & 1) * 2]);
    }
    #undef G2_LDGB
    #undef G2_STSB
    #undef G2_CPA
}

// ---------------- GEMM1: hidden = gelu(x @ W1 + b1) -> bf16 hi/lo -----------
__global__ __launch_bounds__(128, 2)
void gemm1_kernel(const float* __restrict__ x, const float* __restrict__ W1,
                  const float* __restrict__ b1) {
    const int e = blockIdx.z;
    const int cnt = g_counts[e];
    const int row0 = blockIdx.y * 128;
    if (row0 >= cnt) return;
    const int n0 = blockIdx.x * 128;

    __shared__ __align__(128) char smem_buf[2 * STAGE_B];
    const int tid = threadIdx.x;
    const int off_e = g_off[e];

    const int slot = row0 + tid;
    const int tok = g_pairs[e][slot < cnt ? slot : cnt - 1] >> 1;
    const float* axp = x + (size_t)tok * DM;

    float acc[4][8][4];
    #pragma unroll
    for (int i = 0; i < 4; i++)
        #pragma unroll
        for (int j = 0; j < 8; j++)
            #pragma unroll
            for (int q = 0; q < 4; q++) acc[i][j][q] = 0.f;

    gemm1_mainloop(axp, W1 + (size_t)e * DM * FH, n0, smem_buf, acc);

    const int lane = tid & 31, wid = tid >> 5;
    const int wm = (wid >> 1) * 64, wn = (wid & 1) * 64;
    const float* b1e = b1 + (size_t)e * FH + n0;
    const int rem = cnt - row0;

    #pragma unroll
    for (int i = 0; i < 4; i++) {
        #pragma unroll
        for (int j = 0; j < 8; j++) {
            const int col = wn + j * 8 + 2 * (lane & 3);
            const float bb0 = b1e[col], bb1 = b1e[col + 1];
            #pragma unroll
            for (int h = 0; h < 2; h++) {
                const int r = wm + i * 16 + (lane >> 2) + h * 8;
                if (r < rem) {
                    const size_t sl = (size_t)off_e + row0 + r;
                    const float t0 = acc[i][j][2*h]   + bb0;
                    const float t1 = acc[i][j][2*h+1] + bb1;
                    const float q0 = 0.5f * t0 * (1.0f + erff(t0 * 0.70710678118654752440f));
                    const float q1 = 0.5f * t1 * (1.0f + erff(t1 * 0.70710678118654752440f));
                    __nv_bfloat16 h0 = __float2bfloat16(q0), h1 = __float2bfloat16(q1);
                    const float l0 = q0 - __bfloat162float(h0);
                    const float l1 = q1 - __bfloat162float(h1);
                    __nv_bfloat16 o0 = __float2bfloat16(l0), o1 = __float2bfloat16(l1);
                    const uint32_t vh = (uint32_t)__bfloat16_as_ushort(h0) |
                                        ((uint32_t)__bfloat16_as_ushort(h1) << 16);
                    const uint32_t vl = (uint32_t)__bfloat16_as_ushort(o0) |
                                        ((uint32_t)__bfloat16_as_ushort(o1) << 16);
                    *(uint32_t*)(g_hh + sl * FH + n0 + col) = vh;
                    *(uint32_t*)(g_hl + sl * FH + n0 + col) = vl;
                }
            }
        }
    }
}

// ---------------- GEMM2: y = hidden @ W2 + b2 -------------------------------
__global__ __launch_bounds__(128, 2)
void gemm2_kernel(const float* __restrict__ W2, const float* __restrict__ b2) {
    const int e = blockIdx.z;
    const int cnt = g_counts[e];
    const int row0 = blockIdx.y * 128;
    if (row0 >= cnt) return;
    const int n0 = blockIdx.x * 128;

    __shared__ __align__(128) char smem_buf[3 * STAGE_B];
    const int tid = threadIdx.x;
    const int off_e = g_off[e];

    size_t ar = (size_t)(off_e + row0 + tid);
    if (ar > (size_t)(NPAIR - 1)) ar = NPAIR - 1;
    const __nv_bfloat16* ahp = g_hh + ar * FH;
    const __nv_bfloat16* alp = g_hl + ar * FH;

    float acc[4][8][4];
    #pragma unroll
    for (int i = 0; i < 4; i++)
        #pragma unroll
        for (int j = 0; j < 8; j++)
            #pragma unroll
            for (int q = 0; q < 4; q++) acc[i][j][q] = 0.f;

    gemm2_mainloop(ahp, alp, W2 + (size_t)e * FH * DM, n0, smem_buf, acc);

    const int lane = tid & 31, wid = tid >> 5;
    const int wm = (wid >> 1) * 64, wn = (wid & 1) * 64;
    const float* b2e = b2 + (size_t)e * DM + n0;

    #pragma unroll
    for (int i = 0; i < 4; i++) {
        #pragma unroll
        for (int j = 0; j < 8; j++) {
            const int col = wn + j * 8 + 2 * (lane & 3);
            const float bb0 = b2e[col], bb1 = b2e[col + 1];
            #pragma unroll
            for (int h = 0; h < 2; h++) {
                const int r = wm + i * 16 + (lane >> 2) + h * 8;
                if (row0 + r < cnt) {
                    const int pair = g_pairs[e][row0 + r];
                    float2 v;
                    v.x = acc[i][j][2*h]   + bb0;
                    v.y = acc[i][j][2*h+1] + bb1;
                    *(float2*)(g_y + (size_t)pair * DM + n0 + col) = v;
                }
            }
        }
    }
}

// ---------------- combine ----------------------------------------------------
__global__ __launch_bounds__(256) void combine_kernel(float* __restrict__ out) {
    const int per_tok = DM / 4;
    const int i = blockIdx.x * blockDim.x + threadIdx.x;
    if (i >= T_TOK * per_tok) return;
    const int t = i / per_tok;
    const int c = i - t * per_tok;
    const float w0 = g_cw[2*t], w1 = g_cw[2*t + 1];
    const float4* y = (const float4*)g_y;
    const float4 a = y[(size_t)(2*t)     * per_tok + c];
    const float4 b = y[(size_t)(2*t + 1) * per_tok + c];
    float4 r;
    r.x = w0*a.x + w1*b.x;
    r.y = w0*a.y + w1*b.y;
    r.z = w0*a.z + w1*b.z;
    r.w = w0*a.w + w1*b.w;
    ((float4*)out)[i] = r;
}

// ---------------- launch ----------------------------------------------------
extern "C" void kernel_launch(void* const* d_in, const int* in_sizes, int n_in,
                              void* d_out, int out_size) {
    const float* x  = (const float*)d_in[0];
    const float* wg = (const float*)d_in[1];
    const float* W1 = (const float*)d_in[2];
    const float* b1 = (const float*)d_in[3];
    const float* W2 = (const float*)d_in[4];
    const float* b2 = (const float*)d_in[5];
    float* out = (float*)d_out;

    zero_counts_kernel<<<1, 32>>>();
    gate_kernel<<<T_TOK / 8, 256>>>(x, wg);
    prefix_kernel<<<1, 1>>>();
    gemm1_kernel<<<dim3(FH / 128, T_TOK / 128, NE), 128>>>(x, W1, b1);
    gemm2_kernel<<<dim3(DM / 128, T_TOK / 128, NE), 128>>>(W2, b2);
    combine_kernel<<<(T_TOK * (DM / 4) + 255) / 256, 256>>>(out);
}